// round 11
// baseline (speedup 1.0000x reference)
#include <cuda_runtime.h>
#include <cuda_fp16.h>
#include <math.h>
#include <stdint.h>

#define BB 8
#define TT 2048
#define CC 768
#define WDD 512
#define TDD 384
#define CDD 3072
#define HH1 384
#define HHS 1536
#define MTOT (BB*TT)

typedef unsigned int uint;
typedef unsigned long long ull;

// ---------------- scratch (device globals; no runtime alloc) ----------------
__device__ __align__(16) float g_XLN [MTOT*CC];
__device__ __align__(16) float g_TMP [(size_t)MTOT*CDD];
__device__ __align__(16) float g_H1  [MTOT*TDD];
__device__ __align__(16) float g_H2  [MTOT*TDD];
__device__ __align__(16) float g_MIX [BB*TDD*CC];
__device__ __align__(16) float g_X1  [MTOT*CC];
__device__ __align__(16) float g_X2  [MTOT*CC];
__device__ __align__(16) float g_S1  [BB*HH1];
__device__ __align__(16) float g_S2  [BB*HH1];
__device__ __align__(16) float g_SS  [BB*HHS];
// fp16 split operands (A: [hi|hi|lo] along 3K, B: [hi|lo|hi] along 3K)
__device__ __align__(16) __half h_XLN [(size_t)MTOT*2304];
__device__ __align__(16) __half h_ACT [(size_t)MTOT*4608];
__device__ __align__(16) __half h_H2  [(size_t)MTOT*1152];
__device__ __align__(16) __half h_X2  [(size_t)MTOT*2304];
__device__ __align__(16) __half h_H1T [(size_t)BB*TDD*6144];
__device__ __align__(16) __half h_XLNT[(size_t)BB*CC*6144];
__device__ __align__(16) __half h_MIXT[(size_t)BB*CC*1152];
__device__ __align__(16) __half h_Wg1[768*2304], h_Wg2[768*2304], h_Wr1[768*2304];
__device__ __align__(16) __half h_Wm1[384*1152], h_Wm2[384*1152], h_Wr2[768*1152];
__device__ __align__(16) __half h_Wgs[(size_t)3072*2304];
__device__ __align__(16) __half h_Wms[768*4608];

// ---------------- PTX helpers (generic sm_80-class only) ----------------
__device__ __forceinline__ uint s2u(const void* p){
    uint a;
    asm("{ .reg .u64 t; cvta.to.shared.u64 t, %1; cvt.u32.u64 %0, t; }":"=r"(a):"l"(p));
    return a;
}
__device__ __forceinline__ void cpa16(uint s, const void* g){
    asm volatile("cp.async.cg.shared.global [%0], [%1], 16;"::"r"(s),"l"(g));
}
__device__ __forceinline__ void cpa_commit(){ asm volatile("cp.async.commit_group;":::"memory"); }
template<int N> __device__ __forceinline__ void cpa_wait(){
    asm volatile("cp.async.wait_group %0;"::"n"(N):"memory");
}
__device__ __forceinline__ void ldsm4(uint* d, uint addr){
    asm volatile("ldmatrix.sync.aligned.m8n8.x4.shared.b16 {%0,%1,%2,%3}, [%4];"
        : "=r"(d[0]),"=r"(d[1]),"=r"(d[2]),"=r"(d[3]) : "r"(addr));
}
__device__ __forceinline__ void mma16816(float* c, const uint* a, uint b0, uint b1){
    asm volatile("mma.sync.aligned.m16n8k16.row.col.f32.f16.f16.f32 "
        "{%0,%1,%2,%3}, {%4,%5,%6,%7}, {%8,%9}, {%0,%1,%2,%3};"
        : "+f"(c[0]),"+f"(c[1]),"+f"(c[2]),"+f"(c[3])
        : "r"(a[0]),"r"(a[1]),"r"(a[2]),"r"(a[3]), "r"(b0),"r"(b1));
}

// ---------------- HMMA GEMM: C[M,N] = A[M,K'] . B[N,K']^T -------------------
// CTA tile 128 x BN (BN = 128 or 256), 256 thr, warp grid 2(M) x 4(N),
// warp tile 64 x BN/4, k-stage 32, 3-stage cp.async, single sync per stage,
// 80B smem pitch (conflict-free ldmatrix).
// EPI: 0 = +bias(opt), 1 = exact gelu, 2 = +bias(opt) + residual
#define SPITCH 40

template<int EPI, int BN>
__global__ __launch_bounds__(256) void hgemm(
    const __half* __restrict__ A, long sA, int lda,
    const __half* __restrict__ B, long sB, int ldb,
    float* __restrict__ Cm, long sC, int ldc,
    const float* __restrict__ bias,
    const float* __restrict__ Res, long sRes, int K)
{
    constexpr int WN  = BN / 4;          // warp N tile: 32 or 64
    constexpr int NBQ = WN / 16;         // B ldmatrix groups: 2 or 4
    constexpr int NT  = WN / 8;          // mma n-tiles: 4 or 8
    constexpr int STG = (128 + BN) * SPITCH; // halfs per stage

    extern __shared__ __half sm[];
    const int tid = threadIdx.x;
    const int lane = tid & 31, wid = tid >> 5;
    const int wm = wid >> 2, wn = wid & 3;
    const int bz = blockIdx.z;
    const long bm = (long)blockIdx.y * 128;
    const long bn = (long)blockIdx.x * BN;
    const __half* Ag = A + bz * sA + bm * lda;
    const __half* Bg = B + bz * sB + bn * ldb;
    Cm += bz * sC;
    if (EPI == 2) Res += bz * sRes;

    float acc[4][NT][4];
    #pragma unroll
    for (int i = 0; i < 4; i++)
        #pragma unroll
        for (int j = 0; j < NT; j++)
            #pragma unroll
            for (int q = 0; q < 4; q++) acc[i][j][q] = 0.f;

    auto load_stage = [&](int st, int k0){
        __half* base = sm + st * STG;
        #pragma unroll
        for (int i = 0; i < (128 + BN) / 64; i++){
            int cid = i * 256 + tid;
            int row = cid >> 2, seg = cid & 3;
            if (row < 128)
                cpa16(s2u(base + row * SPITCH + seg * 8),
                      Ag + (long)row * lda + k0 + seg * 8);
            else
                cpa16(s2u(base + 128 * SPITCH + (row - 128) * SPITCH + seg * 8),
                      Bg + (long)(row - 128) * ldb + k0 + seg * 8);
        }
    };

    const int nst = K >> 5;
    load_stage(0, 0);  cpa_commit();
    load_stage(1, 32); cpa_commit();

    for (int s = 0; s < nst; s++){
        cpa_wait<1>();
        __syncthreads();
        if (s + 2 < nst) load_stage((s + 2) % 3, (s + 2) << 5);
        cpa_commit();
        const __half* As = sm + (s % 3) * STG;
        const __half* Bs = As + 128 * SPITCH;
        #pragma unroll
        for (int kk = 0; kk < 2; kk++){
            uint a[4][4], b[NBQ][4];
            #pragma unroll
            for (int mt = 0; mt < 4; mt++){
                int r = wm * 64 + mt * 16 + (lane & 7) + ((lane >> 3) & 1) * 8;
                int sg = kk * 2 + (lane >> 4);
                ldsm4(a[mt], s2u(As + r * SPITCH + sg * 8));
            }
            #pragma unroll
            for (int bq = 0; bq < NBQ; bq++){
                int r = wn * WN + bq * 16 + (lane & 7) + ((lane >> 4) & 1) * 8;
                int sg = kk * 2 + ((lane >> 3) & 1);
                ldsm4(b[bq], s2u(Bs + r * SPITCH + sg * 8));
            }
            #pragma unroll
            for (int mt = 0; mt < 4; mt++)
                #pragma unroll
                for (int nt = 0; nt < NT; nt++)
                    mma16816(acc[mt][nt], a[mt], b[nt >> 1][(nt & 1) * 2],
                             b[nt >> 1][(nt & 1) * 2 + 1]);
        }
    }

    #pragma unroll
    for (int mt = 0; mt < 4; mt++){
        #pragma unroll
        for (int hf = 0; hf < 2; hf++){
            long row = bm + wm * 64 + mt * 16 + (lane >> 2) + hf * 8;
            float* Cr = Cm + row * (long)ldc;
            const float* Rr = (EPI == 2) ? (Res + row * (long)ldc) : nullptr;
            #pragma unroll
            for (int nt = 0; nt < NT; nt++){
                long col = bn + wn * WN + nt * 8 + (lane & 3) * 2;
                float v0 = acc[mt][nt][hf * 2 + 0];
                float v1 = acc[mt][nt][hf * 2 + 1];
                if (EPI != 1 && bias){ v0 += bias[col]; v1 += bias[col + 1]; }
                if (EPI == 1){
                    v0 = 0.5f * v0 * (1.f + erff(v0 * 0.70710678118f));
                    v1 = 0.5f * v1 * (1.f + erff(v1 * 0.70710678118f));
                }
                if (EPI == 2){
                    float2 q = *(const float2*)&Rr[col];
                    v0 += q.x; v1 += q.y;
                }
                float2 o; o.x = v0; o.y = v1;
                *(float2*)&Cr[col] = o;
            }
        }
    }
}

#define HSM(BN) (3*(128+(BN))*SPITCH*2)

// ---------------- fp16 split helpers ----------------
__device__ __forceinline__ void split1(float x, uint16_t& h, uint16_t& l){
    __half hb = __float2half_rn(x);
    h = __half_as_ushort(hb);
    l = __half_as_ushort(__float2half_rn(x - __half2float(hb)));
}
__device__ __forceinline__ void split4(float4 v, ull& hu, ull& lu){
    uint16_t h0,h1,h2,h3,l0,l1,l2,l3;
    split1(v.x,h0,l0); split1(v.y,h1,l1); split1(v.z,h2,l2); split1(v.w,h3,l3);
    hu = (ull)h0 | ((ull)h1<<16) | ((ull)h2<<32) | ((ull)h3<<48);
    lu = (ull)l0 | ((ull)l1<<16) | ((ull)l2<<32) | ((ull)l3<<48);
}

// split_row: X[R,K] f32 -> O[R,3K] fp16 [hi|hi|lo]   (block = K/4)
__global__ void split_row_kernel(const float* __restrict__ X, __half* __restrict__ O, int K){
    long r = blockIdx.x;
    int j = threadIdx.x * 4;
    float4 v = *(const float4*)&X[r * K + j];
    ull hu, lu; split4(v, hu, lu);
    __half* o = O + r * (3L * K);
    *(ull*)(o + j)          = hu;
    *(ull*)(o + K + j)      = hu;
    *(ull*)(o + 2L * K + j) = lu;
}

// gate+split: H[R,2K] -> O[R,3K] fp16 [hi|hi|lo], val = a*sigmoid(g)[*S(b)]
__global__ void gate_split_kernel(const float* __restrict__ H, const float* __restrict__ S,
                                  __half* __restrict__ O, int K){
    long r = blockIdx.x;
    int j = threadIdx.x * 4;
    const float* hr = H + r * (2L * K);
    float4 a = *(const float4*)&hr[j];
    float4 g = *(const float4*)&hr[K + j];
    float4 v;
    v.x = a.x / (1.f + expf(-g.x));
    v.y = a.y / (1.f + expf(-g.y));
    v.z = a.z / (1.f + expf(-g.z));
    v.w = a.w / (1.f + expf(-g.w));
    if (S){
        float4 s = *(const float4*)&S[(r / TT) * (long)K + j];
        v.x *= s.x; v.y *= s.y; v.z *= s.z; v.w *= s.w;
    }
    ull hu, lu; split4(v, hu, lu);
    __half* o = O + r * (3L * K);
    *(ull*)(o + j)          = hu;
    *(ull*)(o + K + j)      = hu;
    *(ull*)(o + 2L * K + j) = lu;
}

// LayerNorm: f32 row -> optional f32 + fp16 split [hi|hi|lo], C=768
__global__ __launch_bounds__(256) void ln_kernel(
    const float* __restrict__ X, const float* __restrict__ g,
    const float* __restrict__ b, float* __restrict__ Y, __half* __restrict__ O)
{
    long row = blockIdx.x;
    const float* xr = X + row * CC;
    int t = threadIdx.x;
    float v0 = xr[t], v1 = xr[t + 256], v2 = xr[t + 512];
    float s  = v0 + v1 + v2;
    float s2 = v0*v0 + v1*v1 + v2*v2;
    __shared__ float sh[64];
    #pragma unroll
    for (int o = 16; o > 0; o >>= 1){
        s  += __shfl_down_sync(0xffffffffu, s,  o);
        s2 += __shfl_down_sync(0xffffffffu, s2, o);
    }
    int w = t >> 5, l = t & 31;
    if (l == 0){ sh[w] = s; sh[w + 32] = s2; }
    __syncthreads();
    if (w == 0){
        s  = (l < 8) ? sh[l]      : 0.f;
        s2 = (l < 8) ? sh[l + 32] : 0.f;
        #pragma unroll
        for (int o = 4; o > 0; o >>= 1){
            s  += __shfl_down_sync(0xffffffffu, s,  o);
            s2 += __shfl_down_sync(0xffffffffu, s2, o);
        }
        if (l == 0){ sh[0] = s; sh[1] = s2; }
    }
    __syncthreads();
    float mu  = sh[0] * (1.0f / CC);
    float var = sh[1] * (1.0f / CC) - mu * mu;
    float inv = rsqrtf(var + 1e-6f);
    __half* orow = O + row * 2304L;
    float* yr = Y ? (Y + row * CC) : nullptr;
    #pragma unroll
    for (int q = 0; q < 3; q++){
        int j = t + q * 256;
        float y = (q == 0 ? v0 : (q == 1 ? v1 : v2));
        y = (y - mu) * inv * g[j] + b[j];
        if (Y) yr[j] = y;
        uint16_t h, lo2; split1(y, h, lo2);
        orow[j]        = __ushort_as_half(h);
        orow[768 + j]  = __ushort_as_half(h);
        orow[1536 + j] = __ushort_as_half(lo2);
    }
}

// transpose+split: X[R,Cn] f32 (batched) -> O[Cn,3R] fp16
// AORDER: [hi|hi|lo], else B-order [hi|lo|hi].  block (32,8)
template<bool AORDER>
__global__ void splitT_kernel(const float* __restrict__ X, long sIn,
                              __half* __restrict__ O, long sOut, int R, int Cn)
{
    int bz = blockIdx.z;
    X += (long)bz * sIn;  O += (long)bz * sOut;
    __shared__ float tile[32][33];
    int r0 = blockIdx.y * 32, c0 = blockIdx.x * 32;
    int tx = threadIdx.x, ty = threadIdx.y;
    #pragma unroll
    for (int i = 0; i < 32; i += 8)
        tile[ty + i][tx] = X[(long)(r0 + ty + i) * Cn + c0 + tx];
    __syncthreads();
    #pragma unroll
    for (int i = 0; i < 32; i += 8){
        int c = c0 + ty + i, r = r0 + tx;
        float v = tile[tx][ty + i];
        uint16_t h, lo2; split1(v, h, lo2);
        long base = (long)c * (3L * R);
        O[base + r] = __ushort_as_half(h);
        if (AORDER){
            O[base + R + r]      = __ushort_as_half(h);
            O[base + 2L * R + r] = __ushort_as_half(lo2);
        } else {
            O[base + R + r]      = __ushort_as_half(lo2);
            O[base + 2L * R + r] = __ushort_as_half(h);
        }
    }
}

// ---------------- style vector: S[b,n] = w_row[b] @ sW + sb ----------------
__global__ __launch_bounds__(256) void style_kernel(
    const float* __restrict__ w, int wOff,
    const float* __restrict__ sW, const float* __restrict__ sb,
    float* __restrict__ S, int N)
{
    int b = blockIdx.y;
    int nl = threadIdx.x & 63, kg = threadIdx.x >> 6;
    int n = blockIdx.x * 64 + nl;
    __shared__ float ws[WDD];
    __shared__ float red[256];
    const float* wr = w + (long)b * 2 * WDD + wOff;
    for (int i = threadIdx.x; i < WDD; i += 256) ws[i] = wr[i];
    __syncthreads();
    float acc = 0.f;
    #pragma unroll 4
    for (int k = kg * 128; k < kg * 128 + 128; k++)
        acc = fmaf(ws[k], sW[(long)k * N + n], acc);
    red[threadIdx.x] = acc;
    __syncthreads();
    if (kg == 0)
        S[(long)b * N + n] = red[nl] + red[64+nl] + red[128+nl] + red[192+nl] + sb[n];
}

// ---------------- host orchestration ----------------
extern "C" void kernel_launch(void* const* d_in, const int* in_sizes, int n_in,
                              void* d_out, int out_size)
{
    const float* x     = (const float*)d_in[0];
    const float* w     = (const float*)d_in[1];
    const float* ln1_g = (const float*)d_in[2];
    const float* ln1_b = (const float*)d_in[3];
    const float* ln2_g = (const float*)d_in[4];
    const float* ln2_b = (const float*)d_in[5];
    const float* g1_W  = (const float*)d_in[6];
    const float* g1_b  = (const float*)d_in[7];
    const float* s1_W  = (const float*)d_in[8];
    const float* s1_b  = (const float*)d_in[9];
    const float* m1_W  = (const float*)d_in[10];
    const float* m1_b  = (const float*)d_in[11];
    const float* g2_W  = (const float*)d_in[12];
    const float* g2_b  = (const float*)d_in[13];
    const float* s2_W  = (const float*)d_in[14];
    const float* s2_b  = (const float*)d_in[15];
    const float* m2_W  = (const float*)d_in[16];
    const float* m2_b  = (const float*)d_in[17];
    const float* gs_W  = (const float*)d_in[18];
    const float* gs_b  = (const float*)d_in[19];
    const float* ss_W  = (const float*)d_in[20];
    const float* ss_b  = (const float*)d_in[21];
    const float* ms_W  = (const float*)d_in[22];
    const float* ms_b  = (const float*)d_in[23];
    const float* r1_W  = (const float*)d_in[24];
    const float* r1_b  = (const float*)d_in[25];
    const float* r2_W  = (const float*)d_in[26];
    const float* r2_b  = (const float*)d_in[27];
    float* out = (float*)d_out;

    float *XLN,*TMP,*H1,*H2,*MIX,*X1,*X2,*S1,*S2,*SS;
    __half *XLNh,*ACT,*H2h,*X2h,*H1T,*XLNT,*MIXT;
    __half *Wg1,*Wg2,*Wr1,*Wm1,*Wm2,*Wr2,*Wgs,*Wms;
    cudaGetSymbolAddress((void**)&XLN, g_XLN);   cudaGetSymbolAddress((void**)&TMP, g_TMP);
    cudaGetSymbolAddress((void**)&H1, g_H1);     cudaGetSymbolAddress((void**)&H2, g_H2);
    cudaGetSymbolAddress((void**)&MIX, g_MIX);   cudaGetSymbolAddress((void**)&X1, g_X1);
    cudaGetSymbolAddress((void**)&X2, g_X2);
    cudaGetSymbolAddress((void**)&S1, g_S1);     cudaGetSymbolAddress((void**)&S2, g_S2);
    cudaGetSymbolAddress((void**)&SS, g_SS);
    cudaGetSymbolAddress((void**)&XLNh, h_XLN);  cudaGetSymbolAddress((void**)&ACT, h_ACT);
    cudaGetSymbolAddress((void**)&H2h, h_H2);    cudaGetSymbolAddress((void**)&X2h, h_X2);
    cudaGetSymbolAddress((void**)&H1T, h_H1T);   cudaGetSymbolAddress((void**)&XLNT, h_XLNT);
    cudaGetSymbolAddress((void**)&MIXT, h_MIXT);
    cudaGetSymbolAddress((void**)&Wg1, h_Wg1);   cudaGetSymbolAddress((void**)&Wg2, h_Wg2);
    cudaGetSymbolAddress((void**)&Wr1, h_Wr1);   cudaGetSymbolAddress((void**)&Wm1, h_Wm1);
    cudaGetSymbolAddress((void**)&Wm2, h_Wm2);   cudaGetSymbolAddress((void**)&Wr2, h_Wr2);
    cudaGetSymbolAddress((void**)&Wgs, h_Wgs);   cudaGetSymbolAddress((void**)&Wms, h_Wms);

    cudaFuncSetAttribute(hgemm<0,128>, cudaFuncAttributeMaxDynamicSharedMemorySize, HSM(128));
    cudaFuncSetAttribute(hgemm<1,128>, cudaFuncAttributeMaxDynamicSharedMemorySize, HSM(128));
    cudaFuncSetAttribute(hgemm<0,256>, cudaFuncAttributeMaxDynamicSharedMemorySize, HSM(256));
    cudaFuncSetAttribute(hgemm<2,256>, cudaFuncAttributeMaxDynamicSharedMemorySize, HSM(256));

    dim3 tb(32, 8);

    // weights -> [N,3K] fp16 split (B-order)
    splitT_kernel<false><<<dim3(768/32, 768/32, 1), tb>>>(g1_W, 0, Wg1, 0, 768, 768);
    splitT_kernel<false><<<dim3(768/32, 768/32, 1), tb>>>(g2_W, 0, Wg2, 0, 768, 768);
    splitT_kernel<false><<<dim3(768/32, 768/32, 1), tb>>>(r1_W, 0, Wr1, 0, 768, 768);
    splitT_kernel<false><<<dim3(384/32, 384/32, 1), tb>>>(m1_W, 0, Wm1, 0, 384, 384);
    splitT_kernel<false><<<dim3(384/32, 384/32, 1), tb>>>(m2_W, 0, Wm2, 0, 384, 384);
    splitT_kernel<false><<<dim3(768/32, 384/32, 1), tb>>>(r2_W, 0, Wr2, 0, 384, 768);
    splitT_kernel<false><<<dim3(3072/32, 768/32, 1), tb>>>(gs_W, 0, Wgs, 0, 768, 3072);
    splitT_kernel<false><<<dim3(768/32, 1536/32, 1), tb>>>(ms_W, 0, Wms, 0, 1536, 768);

    // style vectors
    style_kernel<<<dim3(HH1/64, BB), 256>>>(w, 0,   s1_W, s1_b, S1, HH1);
    style_kernel<<<dim3(HH1/64, BB), 256>>>(w, 0,   s2_W, s2_b, S2, HH1);
    style_kernel<<<dim3(HHS/64, BB), 256>>>(w, WDD, ss_W, ss_b, SS, HHS);

    // LN1 -> XLN f32 + fp16 split
    ln_kernel<<<MTOT, 256>>>(x, ln1_g, ln1_b, XLN, XLNh);
    splitT_kernel<false><<<dim3(CC/32, TT/32, BB), tb>>>(
        XLN, (long)TT*CC, XLNT, (long)CC*6144, TT, CC);

    // GLU #1
    hgemm<0,256><<<dim3(CC/256, MTOT/128, 1), 256, HSM(256)>>>(
        XLNh, 0, 2304, Wg1, 0, 2304, TMP, 0, CC, g1_b, nullptr, 0, 2304);
    gate_split_kernel<<<MTOT, HH1/4>>>(TMP, S1, ACT, HH1);
    hgemm<0,128><<<dim3(TDD/128, MTOT/128, 1), 256, HSM(128)>>>(
        ACT, 0, 1152, Wm1, 0, 1152, H1, 0, TDD, m1_b, nullptr, 0, 1152);

    // GLU #2
    hgemm<0,256><<<dim3(CC/256, MTOT/128, 1), 256, HSM(256)>>>(
        XLNh, 0, 2304, Wg2, 0, 2304, TMP, 0, CC, g2_b, nullptr, 0, 2304);
    gate_split_kernel<<<MTOT, HH1/4>>>(TMP, S2, ACT, HH1);
    hgemm<0,128><<<dim3(TDD/128, MTOT/128, 1), 256, HSM(128)>>>(
        ACT, 0, 1152, Wm2, 0, 1152, H2, 0, TDD, m2_b, nullptr, 0, 1152);

    // splits for mix + X1
    splitT_kernel<true ><<<dim3(TDD/32, TT/32, BB), tb>>>(
        H1, (long)TT*TDD, H1T, (long)TDD*6144, TT, TDD);
    split_row_kernel<<<MTOT, TDD/4>>>(H2, H2h, TDD);

    // MIX[b] = gelu(H1[b]^T @ XLN[b])  M=384, N=768, K'=6144 (128-wide for occupancy)
    hgemm<1,128><<<dim3(CC/128, TDD/128, BB), 256, HSM(128)>>>(
        H1T, (long)TDD*6144, 6144, XLNT, (long)CC*6144, 6144,
        MIX, (long)TDD*CC, CC, nullptr, nullptr, 0, 6144);
    splitT_kernel<false><<<dim3(CC/32, TDD/32, BB), tb>>>(
        MIX, (long)TDD*CC, MIXT, (long)CC*1152, TDD, CC);

    // X1[b] = XLN[b] + H2[b] @ MIX[b]  M=2048, N=768, K'=1152
    hgemm<2,256><<<dim3(CC/256, TT/128, BB), 256, HSM(256)>>>(
        H2h, (long)TT*1152, 1152, MIXT, (long)CC*1152, 1152,
        X1, (long)TT*CC, CC, nullptr, XLN, (long)TT*CC, 1152);

    // LN2 -> fp16 split only
    ln_kernel<<<MTOT, 256>>>(X1, ln2_g, ln2_b, nullptr, XLNh);

    // big GLU
    hgemm<0,256><<<dim3(CDD/256, MTOT/128, 1), 256, HSM(256)>>>(
        XLNh, 0, 2304, Wgs, 0, 2304, TMP, 0, CDD, gs_b, nullptr, 0, 2304);
    gate_split_kernel<<<MTOT, HHS/4>>>(TMP, SS, ACT, HHS);
    hgemm<2,256><<<dim3(CC/256, MTOT/128, 1), 256, HSM(256)>>>(
        ACT, 0, 4608, Wms, 0, 4608, X2, 0, CC, ms_b, X1, 0, 4608);

    // final GLU
    split_row_kernel<<<MTOT, CC/4>>>(X2, X2h, CC);
    hgemm<0,256><<<dim3(CC/256, MTOT/128, 1), 256, HSM(256)>>>(
        X2h, 0, 2304, Wr1, 0, 2304, TMP, 0, CC, r1_b, nullptr, 0, 2304);
    gate_split_kernel<<<MTOT, HH1/4>>>(TMP, nullptr, ACT, HH1);
    hgemm<0,256><<<dim3(CC/256, MTOT/128, 1), 256, HSM(256)>>>(
        ACT, 0, 1152, Wr2, 0, 1152, out, 0, CC, r2_b, nullptr, 0, 1152);
}

// round 12
// speedup vs baseline: 1.0219x; 1.0219x over previous
#include <cuda_runtime.h>
#include <cuda_fp16.h>
#include <math.h>
#include <stdint.h>

#define BB 8
#define TT 2048
#define CC 768
#define WDD 512
#define TDD 384
#define CDD 3072
#define HH1 384
#define HHS 1536
#define MTOT (BB*TT)

typedef unsigned int uint;
typedef unsigned long long ull;

// ---------------- scratch (device globals; no runtime alloc) ----------------
__device__ __align__(16) float g_XLN [MTOT*CC];
__device__ __align__(16) float g_H1  [MTOT*TDD];
__device__ __align__(16) float g_MIX [BB*TDD*CC];
__device__ __align__(16) float g_X1  [MTOT*CC];
__device__ __align__(16) float g_S1  [BB*HH1];
__device__ __align__(16) float g_S2  [BB*HH1];
__device__ __align__(16) float g_SS  [BB*HHS];
// fp16 split operands (A: [hi|hi|lo] along 3K, B: [hi|lo|hi] along 3K)
__device__ __align__(16) __half h_XLN [(size_t)MTOT*2304];
__device__ __align__(16) __half h_ACT [(size_t)MTOT*4608];
__device__ __align__(16) __half h_H2  [(size_t)MTOT*1152];
__device__ __align__(16) __half h_X2  [(size_t)MTOT*2304];
__device__ __align__(16) __half h_H1T [(size_t)BB*TDD*6144];
__device__ __align__(16) __half h_XLNT[(size_t)BB*CC*6144];
__device__ __align__(16) __half h_MIXT[(size_t)BB*CC*1152];
__device__ __align__(16) __half h_Wg1[768*2304], h_Wg2[768*2304], h_Wr1[768*2304];
__device__ __align__(16) __half h_Wm1[384*1152], h_Wm2[384*1152], h_Wr2[768*1152];
__device__ __align__(16) __half h_Wgs[(size_t)3072*2304];
__device__ __align__(16) __half h_Wms[768*4608];

// ---------------- PTX helpers (generic sm_80-class only) ----------------
__device__ __forceinline__ uint s2u(const void* p){
    uint a;
    asm("{ .reg .u64 t; cvta.to.shared.u64 t, %1; cvt.u32.u64 %0, t; }":"=r"(a):"l"(p));
    return a;
}
__device__ __forceinline__ void cpa16(uint s, const void* g){
    asm volatile("cp.async.cg.shared.global [%0], [%1], 16;"::"r"(s),"l"(g));
}
__device__ __forceinline__ void cpa_commit(){ asm volatile("cp.async.commit_group;":::"memory"); }
template<int N> __device__ __forceinline__ void cpa_wait(){
    asm volatile("cp.async.wait_group %0;"::"n"(N):"memory");
}
__device__ __forceinline__ void ldsm4(uint* d, uint addr){
    asm volatile("ldmatrix.sync.aligned.m8n8.x4.shared.b16 {%0,%1,%2,%3}, [%4];"
        : "=r"(d[0]),"=r"(d[1]),"=r"(d[2]),"=r"(d[3]) : "r"(addr));
}
__device__ __forceinline__ void mma16816(float* c, const uint* a, uint b0, uint b1){
    asm volatile("mma.sync.aligned.m16n8k16.row.col.f32.f16.f16.f32 "
        "{%0,%1,%2,%3}, {%4,%5,%6,%7}, {%8,%9}, {%0,%1,%2,%3};"
        : "+f"(c[0]),"+f"(c[1]),"+f"(c[2]),"+f"(c[3])
        : "r"(a[0]),"r"(a[1]),"r"(a[2]),"r"(a[3]), "r"(b0),"r"(b1));
}
__device__ __forceinline__ void split1(float x, uint16_t& h, uint16_t& l){
    __half hb = __float2half_rn(x);
    h = __half_as_ushort(hb);
    l = __half_as_ushort(__float2half_rn(x - __half2float(hb)));
}

// ---------------- HMMA GEMM: C[M,N] = A[M,K'] . B[N,K']^T -------------------
// 128x128 CTA tile, 256 thr, warp grid 2(M)x4(N), warp tile 64x32, k-stage 32,
// 4-stage cp.async, one sync per stage, 80B pitch, forced 2 CTA/SM.
// EPI: 0 f32 +bias(opt)          1 f32 exact-gelu
//      2 f32 +bias(opt)+residual 3 half gate: act=(c0+ba)*sigmoid(c1+bg)[*S] -> split
//      4 half bias+residual -> split      5 half bias -> split
#define SPITCH 40
#define STG (256*SPITCH)
#define HSMEMB (4*STG*2)   // 81920 bytes

template<int EPI>
__global__ __launch_bounds__(256, 2) void hgemm(
    const __half* __restrict__ A, long sA, int lda,
    const __half* __restrict__ B, long sB, int ldb,
    void* __restrict__ Cout, long sC, int ldc,
    const float* __restrict__ bias,
    const float* __restrict__ Res, long sRes, int K)
{
    extern __shared__ __half sm[];
    const int tid = threadIdx.x;
    const int lane = tid & 31, wid = tid >> 5;
    const int wm = wid >> 2, wn = wid & 3;
    const int bz = blockIdx.z;
    const long bm = (long)blockIdx.y * 128;
    const long bn = (long)blockIdx.x * 128;
    const __half* Ag = A + bz * sA + bm * lda;
    const __half* Bg = B + bz * sB + bn * ldb;
    float*  Cf = (float*)Cout + bz * sC;
    __half* Ch = (__half*)Cout;          // half outputs are never batched

    float acc[4][4][4];
    #pragma unroll
    for (int i = 0; i < 4; i++)
        #pragma unroll
        for (int j = 0; j < 4; j++)
            #pragma unroll
            for (int q = 0; q < 4; q++) acc[i][j][q] = 0.f;

    auto load_stage = [&](int st, int k0){
        __half* base = sm + st * STG;
        #pragma unroll
        for (int i = 0; i < 4; i++){
            int cid = i * 256 + tid;
            int row = cid >> 2, seg = cid & 3;
            const __half* src = (row < 128)
                ? Ag + (long)row * lda + k0 + seg * 8
                : Bg + (long)(row - 128) * ldb + k0 + seg * 8;
            cpa16(s2u(base + row * SPITCH + seg * 8), src);
        }
    };

    const int nst = K >> 5;                // all call sites: nst >= 36
    load_stage(0, 0);  cpa_commit();
    load_stage(1, 32); cpa_commit();
    load_stage(2, 64); cpa_commit();

    for (int s = 0; s < nst; s++){
        cpa_wait<2>();
        __syncthreads();
        if (s + 3 < nst){ load_stage((s + 3) & 3, (s + 3) << 5); cpa_commit(); }
        const __half* As = sm + (s & 3) * STG;
        const __half* Bs = As + 128 * SPITCH;
        #pragma unroll
        for (int kk = 0; kk < 2; kk++){
            uint a[4][4], b[2][4];
            #pragma unroll
            for (int mt = 0; mt < 4; mt++){
                int r = wm * 64 + mt * 16 + (lane & 7) + ((lane >> 3) & 1) * 8;
                int sg = kk * 2 + (lane >> 4);
                ldsm4(a[mt], s2u(As + r * SPITCH + sg * 8));
            }
            #pragma unroll
            for (int bq = 0; bq < 2; bq++){
                int r = wn * 32 + bq * 16 + (lane & 7) + ((lane >> 4) & 1) * 8;
                int sg = kk * 2 + ((lane >> 3) & 1);
                ldsm4(b[bq], s2u(Bs + r * SPITCH + sg * 8));
            }
            #pragma unroll
            for (int mt = 0; mt < 4; mt++)
                #pragma unroll
                for (int nt = 0; nt < 4; nt++)
                    mma16816(acc[mt][nt], a[mt], b[nt >> 1][(nt & 1) * 2],
                             b[nt >> 1][(nt & 1) * 2 + 1]);
        }
    }

    #pragma unroll
    for (int mt = 0; mt < 4; mt++){
        #pragma unroll
        for (int hf = 0; hf < 2; hf++){
            long row = bm + wm * 64 + mt * 16 + (lane >> 2) + hf * 8;
            #pragma unroll
            for (int nt = 0; nt < 4; nt++){
                long col = bn + wn * 32 + nt * 8 + (lane & 3) * 2;
                float v0 = acc[mt][nt][hf * 2 + 0];
                float v1 = acc[mt][nt][hf * 2 + 1];
                if constexpr (EPI == 0 || EPI == 2){
                    if (bias){ v0 += bias[col]; v1 += bias[col + 1]; }
                    if (EPI == 2){
                        float2 q = *(const float2*)&Res[bz * sRes + row * ldc + col];
                        v0 += q.x; v1 += q.y;
                    }
                    float2 o; o.x = v0; o.y = v1;
                    *(float2*)&Cf[row * (long)ldc + col] = o;
                } else if constexpr (EPI == 1){
                    v0 = 0.5f * v0 * (1.f + erff(v0 * 0.70710678118f));
                    v1 = 0.5f * v1 * (1.f + erff(v1 * 0.70710678118f));
                    float2 o; o.x = v0; o.y = v1;
                    *(float2*)&Cf[row * (long)ldc + col] = o;
                } else if constexpr (EPI == 3){
                    // paired cols: (col,col+1) = (a_j, g_j), j = col>>1; ldc = Kout
                    long j = col >> 1;
                    float av = v0 + bias[j];
                    float gv = v1 + bias[j + ldc];
                    float act = av / (1.f + expf(-gv));
                    if (Res) act *= Res[(row / TT) * (long)ldc + j];
                    uint16_t h, l; split1(act, h, l);
                    __half* o = Ch + row * (3L * ldc);
                    o[j]            = __ushort_as_half(h);
                    o[j + ldc]      = __ushort_as_half(h);
                    o[j + 2 * ldc]  = __ushort_as_half(l);
                } else {
                    // EPI 4/5: split-write pair (col,col+1); ldc = N
                    if (bias){ v0 += bias[col]; v1 += bias[col + 1]; }
                    if (EPI == 4){
                        float2 q = *(const float2*)&Res[row * (long)ldc + col];
                        v0 += q.x; v1 += q.y;
                    }
                    uint16_t h0, l0, h1, l1;
                    split1(v0, h0, l0); split1(v1, h1, l1);
                    __half* o = Ch + row * (3L * ldc) + col;
                    uint hp = (uint)h0 | ((uint)h1 << 16);
                    uint lp = (uint)l0 | ((uint)l1 << 16);
                    *(uint*)(o)           = hp;
                    *(uint*)(o + ldc)     = hp;
                    *(uint*)(o + 2 * ldc) = lp;
                }
            }
        }
    }
}

// ---------------- LayerNorm: f32 row -> optional f32 + fp16 split ----------
__global__ __launch_bounds__(256) void ln_kernel(
    const float* __restrict__ X, const float* __restrict__ g,
    const float* __restrict__ b, float* __restrict__ Y, __half* __restrict__ O)
{
    long row = blockIdx.x;
    const float* xr = X + row * CC;
    int t = threadIdx.x;
    float v0 = xr[t], v1 = xr[t + 256], v2 = xr[t + 512];
    float s  = v0 + v1 + v2;
    float s2 = v0*v0 + v1*v1 + v2*v2;
    __shared__ float sh[64];
    #pragma unroll
    for (int o = 16; o > 0; o >>= 1){
        s  += __shfl_down_sync(0xffffffffu, s,  o);
        s2 += __shfl_down_sync(0xffffffffu, s2, o);
    }
    int w = t >> 5, l = t & 31;
    if (l == 0){ sh[w] = s; sh[w + 32] = s2; }
    __syncthreads();
    if (w == 0){
        s  = (l < 8) ? sh[l]      : 0.f;
        s2 = (l < 8) ? sh[l + 32] : 0.f;
        #pragma unroll
        for (int o = 4; o > 0; o >>= 1){
            s  += __shfl_down_sync(0xffffffffu, s,  o);
            s2 += __shfl_down_sync(0xffffffffu, s2, o);
        }
        if (l == 0){ sh[0] = s; sh[1] = s2; }
    }
    __syncthreads();
    float mu  = sh[0] * (1.0f / CC);
    float var = sh[1] * (1.0f / CC) - mu * mu;
    float inv = rsqrtf(var + 1e-6f);
    __half* orow = O + row * 2304L;
    float* yr = Y ? (Y + row * CC) : nullptr;
    #pragma unroll
    for (int q = 0; q < 3; q++){
        int j = t + q * 256;
        float y = (q == 0 ? v0 : (q == 1 ? v1 : v2));
        y = (y - mu) * inv * g[j] + b[j];
        if (Y) yr[j] = y;
        uint16_t h, lo2; split1(y, h, lo2);
        orow[j]        = __ushort_as_half(h);
        orow[768 + j]  = __ushort_as_half(h);
        orow[1536 + j] = __ushort_as_half(lo2);
    }
}

// transpose+split: X[R,Cn] f32 (batched) -> O[Cn,3R] fp16
// AORDER: [hi|hi|lo], else B-order [hi|lo|hi].  block (32,8)
template<bool AORDER>
__global__ void splitT_kernel(const float* __restrict__ X, long sIn,
                              __half* __restrict__ O, long sOut, int R, int Cn)
{
    int bz = blockIdx.z;
    X += (long)bz * sIn;  O += (long)bz * sOut;
    __shared__ float tile[32][33];
    int r0 = blockIdx.y * 32, c0 = blockIdx.x * 32;
    int tx = threadIdx.x, ty = threadIdx.y;
    #pragma unroll
    for (int i = 0; i < 32; i += 8)
        tile[ty + i][tx] = X[(long)(r0 + ty + i) * Cn + c0 + tx];
    __syncthreads();
    #pragma unroll
    for (int i = 0; i < 32; i += 8){
        int c = c0 + ty + i, r = r0 + tx;
        float v = tile[tx][ty + i];
        uint16_t h, lo2; split1(v, h, lo2);
        long base = (long)c * (3L * R);
        O[base + r] = __ushort_as_half(h);
        if (AORDER){
            O[base + R + r]      = __ushort_as_half(h);
            O[base + 2L * R + r] = __ushort_as_half(lo2);
        } else {
            O[base + R + r]      = __ushort_as_half(lo2);
            O[base + 2L * R + r] = __ushort_as_half(h);
        }
    }
}

// transpose+split with gate-pairing: W[K, 2Kh] -> O[2Kh, 3K] B-order,
// output row for orig col c: c<Kh ? 2c : 2(c-Kh)+1
__global__ void splitT_pair_kernel(const float* __restrict__ X,
                                   __half* __restrict__ O, int R, int Cn, int Kh)
{
    __shared__ float tile[32][33];
    int r0 = blockIdx.y * 32, c0 = blockIdx.x * 32;
    int tx = threadIdx.x, ty = threadIdx.y;
    #pragma unroll
    for (int i = 0; i < 32; i += 8)
        tile[ty + i][tx] = X[(long)(r0 + ty + i) * Cn + c0 + tx];
    __syncthreads();
    #pragma unroll
    for (int i = 0; i < 32; i += 8){
        int c = c0 + ty + i, r = r0 + tx;
        int nn = (c < Kh) ? (2 * c) : (2 * (c - Kh) + 1);
        float v = tile[tx][ty + i];
        uint16_t h, lo2; split1(v, h, lo2);
        long base = (long)nn * (3L * R);
        O[base + r]          = __ushort_as_half(h);
        O[base + R + r]      = __ushort_as_half(lo2);
        O[base + 2L * R + r] = __ushort_as_half(h);
    }
}

// ---------------- style vector: S[b,n] = w_row[b] @ sW + sb ----------------
__global__ __launch_bounds__(256) void style_kernel(
    const float* __restrict__ w, int wOff,
    const float* __restrict__ sW, const float* __restrict__ sb,
    float* __restrict__ S, int N)
{
    int b = blockIdx.y;
    int nl = threadIdx.x & 63, kg = threadIdx.x >> 6;
    int n = blockIdx.x * 64 + nl;
    __shared__ float ws[WDD];
    __shared__ float red[256];
    const float* wr = w + (long)b * 2 * WDD + wOff;
    for (int i = threadIdx.x; i < WDD; i += 256) ws[i] = wr[i];
    __syncthreads();
    float acc = 0.f;
    #pragma unroll 4
    for (int k = kg * 128; k < kg * 128 + 128; k++)
        acc = fmaf(ws[k], sW[(long)k * N + n], acc);
    red[threadIdx.x] = acc;
    __syncthreads();
    if (kg == 0)
        S[(long)b * N + n] = red[nl] + red[64+nl] + red[128+nl] + red[192+nl] + sb[n];
}

// ---------------- host orchestration ----------------
extern "C" void kernel_launch(void* const* d_in, const int* in_sizes, int n_in,
                              void* d_out, int out_size)
{
    const float* x     = (const float*)d_in[0];
    const float* w     = (const float*)d_in[1];
    const float* ln1_g = (const float*)d_in[2];
    const float* ln1_b = (const float*)d_in[3];
    const float* ln2_g = (const float*)d_in[4];
    const float* ln2_b = (const float*)d_in[5];
    const float* g1_W  = (const float*)d_in[6];
    const float* g1_b  = (const float*)d_in[7];
    const float* s1_W  = (const float*)d_in[8];
    const float* s1_b  = (const float*)d_in[9];
    const float* m1_W  = (const float*)d_in[10];
    const float* m1_b  = (const float*)d_in[11];
    const float* g2_W  = (const float*)d_in[12];
    const float* g2_b  = (const float*)d_in[13];
    const float* s2_W  = (const float*)d_in[14];
    const float* s2_b  = (const float*)d_in[15];
    const float* m2_W  = (const float*)d_in[16];
    const float* m2_b  = (const float*)d_in[17];
    const float* gs_W  = (const float*)d_in[18];
    const float* gs_b  = (const float*)d_in[19];
    const float* ss_W  = (const float*)d_in[20];
    const float* ss_b  = (const float*)d_in[21];
    const float* ms_W  = (const float*)d_in[22];
    const float* ms_b  = (const float*)d_in[23];
    const float* r1_W  = (const float*)d_in[24];
    const float* r1_b  = (const float*)d_in[25];
    const float* r2_W  = (const float*)d_in[26];
    const float* r2_b  = (const float*)d_in[27];
    float* out = (float*)d_out;

    float *XLN,*H1,*MIX,*X1,*S1,*S2,*SS;
    __half *XLNh,*ACT,*H2h,*X2h,*H1T,*XLNT,*MIXT;
    __half *Wg1,*Wg2,*Wr1,*Wm1,*Wm2,*Wr2,*Wgs,*Wms;
    cudaGetSymbolAddress((void**)&XLN, g_XLN);
    cudaGetSymbolAddress((void**)&H1, g_H1);
    cudaGetSymbolAddress((void**)&MIX, g_MIX);   cudaGetSymbolAddress((void**)&X1, g_X1);
    cudaGetSymbolAddress((void**)&S1, g_S1);     cudaGetSymbolAddress((void**)&S2, g_S2);
    cudaGetSymbolAddress((void**)&SS, g_SS);
    cudaGetSymbolAddress((void**)&XLNh, h_XLN);  cudaGetSymbolAddress((void**)&ACT, h_ACT);
    cudaGetSymbolAddress((void**)&H2h, h_H2);    cudaGetSymbolAddress((void**)&X2h, h_X2);
    cudaGetSymbolAddress((void**)&H1T, h_H1T);   cudaGetSymbolAddress((void**)&XLNT, h_XLNT);
    cudaGetSymbolAddress((void**)&MIXT, h_MIXT);
    cudaGetSymbolAddress((void**)&Wg1, h_Wg1);   cudaGetSymbolAddress((void**)&Wg2, h_Wg2);
    cudaGetSymbolAddress((void**)&Wr1, h_Wr1);   cudaGetSymbolAddress((void**)&Wm1, h_Wm1);
    cudaGetSymbolAddress((void**)&Wm2, h_Wm2);   cudaGetSymbolAddress((void**)&Wr2, h_Wr2);
    cudaGetSymbolAddress((void**)&Wgs, h_Wgs);   cudaGetSymbolAddress((void**)&Wms, h_Wms);

    cudaFuncSetAttribute(hgemm<0>, cudaFuncAttributeMaxDynamicSharedMemorySize, HSMEMB);
    cudaFuncSetAttribute(hgemm<1>, cudaFuncAttributeMaxDynamicSharedMemorySize, HSMEMB);
    cudaFuncSetAttribute(hgemm<2>, cudaFuncAttributeMaxDynamicSharedMemorySize, HSMEMB);
    cudaFuncSetAttribute(hgemm<3>, cudaFuncAttributeMaxDynamicSharedMemorySize, HSMEMB);
    cudaFuncSetAttribute(hgemm<4>, cudaFuncAttributeMaxDynamicSharedMemorySize, HSMEMB);
    cudaFuncSetAttribute(hgemm<5>, cudaFuncAttributeMaxDynamicSharedMemorySize, HSMEMB);

    dim3 tb(32, 8);

    // gate weights -> paired [2Kh, 3K]; others -> plain B-order [N, 3K]
    splitT_pair_kernel<<<dim3(768/32, 768/32), tb>>>(g1_W, Wg1, 768, 768, 384);
    splitT_pair_kernel<<<dim3(768/32, 768/32), tb>>>(g2_W, Wg2, 768, 768, 384);
    splitT_pair_kernel<<<dim3(768/32, 768/32), tb>>>(r1_W, Wr1, 768, 768, 384);
    splitT_pair_kernel<<<dim3(3072/32, 768/32), tb>>>(gs_W, Wgs, 768, 3072, 1536);
    splitT_kernel<false><<<dim3(384/32, 384/32, 1), tb>>>(m1_W, 0, Wm1, 0, 384, 384);
    splitT_kernel<false><<<dim3(384/32, 384/32, 1), tb>>>(m2_W, 0, Wm2, 0, 384, 384);
    splitT_kernel<false><<<dim3(768/32, 384/32, 1), tb>>>(r2_W, 0, Wr2, 0, 384, 768);
    splitT_kernel<false><<<dim3(768/32, 1536/32, 1), tb>>>(ms_W, 0, Wms, 0, 1536, 768);

    // style vectors
    style_kernel<<<dim3(HH1/64, BB), 256>>>(w, 0,   s1_W, s1_b, S1, HH1);
    style_kernel<<<dim3(HH1/64, BB), 256>>>(w, 0,   s2_W, s2_b, S2, HH1);
    style_kernel<<<dim3(HHS/64, BB), 256>>>(w, WDD, ss_W, ss_b, SS, HHS);

    // LN1 -> XLN f32 + fp16 split
    ln_kernel<<<MTOT, 256>>>(x, ln1_g, ln1_b, XLN, XLNh);
    splitT_kernel<false><<<dim3(CC/32, TT/32, BB), tb>>>(
        XLN, (long)TT*CC, XLNT, (long)CC*6144, TT, CC);

    // GLU #1: fused gate -> ACT ; H1 = ACT@m1_W + b (f32, needed transposed)
    hgemm<3><<<dim3(CC/128, MTOT/128, 1), 256, HSMEMB>>>(
        XLNh, 0, 2304, Wg1, 0, 2304, ACT, 0, HH1, g1_b, S1, 0, 2304);
    hgemm<0><<<dim3(TDD/128, MTOT/128, 1), 256, HSMEMB>>>(
        ACT, 0, 1152, Wm1, 0, 1152, H1, 0, TDD, m1_b, nullptr, 0, 1152);

    // GLU #2: fused gate -> ACT ; H2h = split(ACT@m2_W + b) directly
    hgemm<3><<<dim3(CC/128, MTOT/128, 1), 256, HSMEMB>>>(
        XLNh, 0, 2304, Wg2, 0, 2304, ACT, 0, HH1, g2_b, S2, 0, 2304);
    hgemm<5><<<dim3(TDD/128, MTOT/128, 1), 256, HSMEMB>>>(
        ACT, 0, 1152, Wm2, 0, 1152, H2h, 0, TDD, m2_b, nullptr, 0, 1152);

    // transpose-split H1 for mix
    splitT_kernel<true ><<<dim3(TDD/32, TT/32, BB), tb>>>(
        H1, (long)TT*TDD, H1T, (long)TDD*6144, TT, TDD);

    // MIX[b] = gelu(H1[b]^T @ XLN[b])  M=384, N=768, K'=6144
    hgemm<1><<<dim3(CC/128, TDD/128, BB), 256, HSMEMB>>>(
        H1T, (long)TDD*6144, 6144, XLNT, (long)CC*6144, 6144,
        MIX, (long)TDD*CC, CC, nullptr, nullptr, 0, 6144);
    splitT_kernel<false><<<dim3(CC/32, TDD/32, BB), tb>>>(
        MIX, (long)TDD*CC, MIXT, (long)CC*1152, TDD, CC);

    // X1[b] = XLN[b] + H2[b] @ MIX[b]  (f32; feeds LN2 + ms residual)
    hgemm<2><<<dim3(CC/128, TT/128, BB), 256, HSMEMB>>>(
        H2h, (long)TT*1152, 1152, MIXT, (long)CC*1152, 1152,
        X1, (long)TT*CC, CC, nullptr, XLN, (long)TT*CC, 1152);

    // LN2 -> fp16 split only
    ln_kernel<<<MTOT, 256>>>(X1, ln2_g, ln2_b, nullptr, XLNh);

    // big GLU: fused gate (N=3072) -> ACT ; X2h = split(X1 + ACT@ms_W + b)
    hgemm<3><<<dim3(CDD/128, MTOT/128, 1), 256, HSMEMB>>>(
        XLNh, 0, 2304, Wgs, 0, 2304, ACT, 0, HHS, gs_b, SS, 0, 2304);
    hgemm<4><<<dim3(CC/128, MTOT/128, 1), 256, HSMEMB>>>(
        ACT, 0, 4608, Wms, 0, 4608, X2h, 0, CC, ms_b, X1, 0, 4608);

    // final GLU: fused gate (no style) -> ACT ; out = ACT@r2_W + b
    hgemm<3><<<dim3(CC/128, MTOT/128, 1), 256, HSMEMB>>>(
        X2h, 0, 2304, Wr1, 0, 2304, ACT, 0, HH1, r1_b, nullptr, 0, 2304);
    hgemm<0><<<dim3(CC/128, MTOT/128, 1), 256, HSMEMB>>>(
        ACT, 0, 1152, Wr2, 0, 1152, out, 0, CC, r2_b, nullptr, 0, 1152);
}

// round 14
// speedup vs baseline: 1.0389x; 1.0167x over previous
#include <cuda_runtime.h>
#include <cuda_fp16.h>
#include <math.h>
#include <stdint.h>

#define BB 8
#define TT 2048
#define CC 768
#define WDD 512
#define TDD 384
#define CDD 3072
#define HH1 384
#define HHS 1536
#define MTOT (BB*TT)

typedef unsigned int uint;
typedef unsigned long long ull;

// ---------------- scratch (device globals; no runtime alloc) ----------------
__device__ __align__(16) float g_XLN [MTOT*CC];
__device__ __align__(16) float g_H1  [MTOT*TDD];
__device__ __align__(16) float g_MIX [BB*TDD*CC];
__device__ __align__(16) float g_X1  [MTOT*CC];
__device__ __align__(16) float g_S1  [BB*HH1];
__device__ __align__(16) float g_S2  [BB*HH1];
__device__ __align__(16) float g_SS  [BB*HHS];
// fp16 split operands (A: [hi|hi|lo] along 3K, B: [hi|lo|hi] along 3K)
__device__ __align__(16) __half h_XLN [(size_t)MTOT*2304];
__device__ __align__(16) __half h_ACT [(size_t)MTOT*4608];
__device__ __align__(16) __half h_H2  [(size_t)MTOT*1152];
__device__ __align__(16) __half h_X2  [(size_t)MTOT*2304];
__device__ __align__(16) __half h_H1T [(size_t)BB*TDD*6144];
__device__ __align__(16) __half h_XLNT[(size_t)BB*CC*6144];
__device__ __align__(16) __half h_MIXT[(size_t)BB*CC*1152];
__device__ __align__(16) __half h_Wg1[768*2304], h_Wg2[768*2304], h_Wr1[768*2304];
__device__ __align__(16) __half h_Wm1[384*1152], h_Wm2[384*1152], h_Wr2[768*1152];
__device__ __align__(16) __half h_Wgs[(size_t)3072*2304];
__device__ __align__(16) __half h_Wms[768*4608];

// ---------------- PTX helpers (generic sm_80-class only) ----------------
__device__ __forceinline__ uint s2u(const void* p){
    uint a;
    asm("{ .reg .u64 t; cvta.to.shared.u64 t, %1; cvt.u32.u64 %0, t; }":"=r"(a):"l"(p));
    return a;
}
__device__ __forceinline__ void cpa16(uint s, const void* g){
    asm volatile("cp.async.cg.shared.global [%0], [%1], 16;"::"r"(s),"l"(g));
}
__device__ __forceinline__ void cpa_commit(){ asm volatile("cp.async.commit_group;":::"memory"); }
template<int N> __device__ __forceinline__ void cpa_wait(){
    asm volatile("cp.async.wait_group %0;"::"n"(N):"memory");
}
__device__ __forceinline__ void ldsm4(uint* d, uint addr){
    asm volatile("ldmatrix.sync.aligned.m8n8.x4.shared.b16 {%0,%1,%2,%3}, [%4];"
        : "=r"(d[0]),"=r"(d[1]),"=r"(d[2]),"=r"(d[3]) : "r"(addr));
}
__device__ __forceinline__ void mma16816(float* c, const uint* a, uint b0, uint b1){
    asm volatile("mma.sync.aligned.m16n8k16.row.col.f32.f16.f16.f32 "
        "{%0,%1,%2,%3}, {%4,%5,%6,%7}, {%8,%9}, {%0,%1,%2,%3};"
        : "+f"(c[0]),"+f"(c[1]),"+f"(c[2]),"+f"(c[3])
        : "r"(a[0]),"r"(a[1]),"r"(a[2]),"r"(a[3]), "r"(b0),"r"(b1));
}
__device__ __forceinline__ void split1(float x, uint16_t& h, uint16_t& l){
    __half hb = __float2half_rn(x);
    h = __half_as_ushort(hb);
    l = __half_as_ushort(__float2half_rn(x - __half2float(hb)));
}

// ---------------- HMMA GEMM: C[M,N] = A[M,K'] . B[N,K']^T -------------------
// 128x128 CTA tile, 256 thr, warp grid 2(M)x4(N), warp tile 64x32, k-stage 32,
// 3-stage cp.async (R10 winner structure), 80B pitch, NO occupancy forcing.
// EPI: 0 f32 +bias(opt)            1 f32 exact-gelu
//      2 f32 +bias(opt)+residual   3 half gate: (c0+ba)*sigmoid(c1+bg)[*S] -> split
//      4 half bias+residual->split 5 half bias->split
#define SPITCH 40
#define STG (256*SPITCH)
#define HSMEMB (3*STG*2)   // 61440 bytes

template<int EPI>
__global__ __launch_bounds__(256) void hgemm(
    const __half* __restrict__ A, long sA, int lda,
    const __half* __restrict__ B, long sB, int ldb,
    void* __restrict__ Cout, long sC, int ldc,
    const float* __restrict__ bias,
    const float* __restrict__ Res, long sRes, int K)
{
    extern __shared__ __half sm[];
    const int tid = threadIdx.x;
    const int lane = tid & 31, wid = tid >> 5;
    const int wm = wid >> 2, wn = wid & 3;
    const int bz = blockIdx.z;
    const long bm = (long)blockIdx.y * 128;
    const long bn = (long)blockIdx.x * 128;
    const __half* Ag = A + bz * sA + bm * lda;
    const __half* Bg = B + bz * sB + bn * ldb;
    float*  Cf = (float*)Cout + bz * sC;
    __half* Ch = (__half*)Cout;          // half outputs are never batched

    float acc[4][4][4];
    #pragma unroll
    for (int i = 0; i < 4; i++)
        #pragma unroll
        for (int j = 0; j < 4; j++)
            #pragma unroll
            for (int q = 0; q < 4; q++) acc[i][j][q] = 0.f;

    auto load_stage = [&](int st, int k0){
        __half* base = sm + st * STG;
        #pragma unroll
        for (int i = 0; i < 4; i++){
            int cid = i * 256 + tid;
            int row = cid >> 2, seg = cid & 3;
            const __half* src = (row < 128)
                ? Ag + (long)row * lda + k0 + seg * 8
                : Bg + (long)(row - 128) * ldb + k0 + seg * 8;
            cpa16(s2u(base + row * SPITCH + seg * 8), src);
        }
    };

    const int nst = K >> 5;
    load_stage(0, 0);  cpa_commit();
    load_stage(1, 32); cpa_commit();

    for (int s = 0; s < nst; s++){
        if (s + 2 < nst) load_stage((s + 2) % 3, (s + 2) << 5);
        cpa_commit();
        cpa_wait<2>();
        __syncthreads();
        const __half* As = sm + (s % 3) * STG;
        const __half* Bs = As + 128 * SPITCH;
        #pragma unroll
        for (int kk = 0; kk < 2; kk++){
            uint a[4][4], b[2][4];
            #pragma unroll
            for (int mt = 0; mt < 4; mt++){
                int r = wm * 64 + mt * 16 + (lane & 7) + ((lane >> 3) & 1) * 8;
                int sg = kk * 2 + (lane >> 4);
                ldsm4(a[mt], s2u(As + r * SPITCH + sg * 8));
            }
            #pragma unroll
            for (int bq = 0; bq < 2; bq++){
                int r = wn * 32 + bq * 16 + (lane & 7) + ((lane >> 4) & 1) * 8;
                int sg = kk * 2 + ((lane >> 3) & 1);
                ldsm4(b[bq], s2u(Bs + r * SPITCH + sg * 8));
            }
            #pragma unroll
            for (int mt = 0; mt < 4; mt++)
                #pragma unroll
                for (int nt = 0; nt < 4; nt++)
                    mma16816(acc[mt][nt], a[mt], b[nt >> 1][(nt & 1) * 2],
                             b[nt >> 1][(nt & 1) * 2 + 1]);
        }
        __syncthreads();
    }

    #pragma unroll
    for (int mt = 0; mt < 4; mt++){
        #pragma unroll
        for (int hf = 0; hf < 2; hf++){
            long row = bm + wm * 64 + mt * 16 + (lane >> 2) + hf * 8;
            #pragma unroll
            for (int nt = 0; nt < 4; nt++){
                long col = bn + wn * 32 + nt * 8 + (lane & 3) * 2;
                float v0 = acc[mt][nt][hf * 2 + 0];
                float v1 = acc[mt][nt][hf * 2 + 1];
                if constexpr (EPI == 0 || EPI == 2){
                    if (bias){ v0 += bias[col]; v1 += bias[col + 1]; }
                    if (EPI == 2){
                        float2 q = *(const float2*)&Res[bz * sRes + row * ldc + col];
                        v0 += q.x; v1 += q.y;
                    }
                    float2 o; o.x = v0; o.y = v1;
                    *(float2*)&Cf[row * (long)ldc + col] = o;
                } else if constexpr (EPI == 1){
                    v0 = 0.5f * v0 * (1.f + erff(v0 * 0.70710678118f));
                    v1 = 0.5f * v1 * (1.f + erff(v1 * 0.70710678118f));
                    float2 o; o.x = v0; o.y = v1;
                    *(float2*)&Cf[row * (long)ldc + col] = o;
                } else if constexpr (EPI == 3){
                    // paired cols: (col,col+1) = (a_j, g_j), j = col>>1; ldc = Kh
                    long j = col >> 1;
                    float av = v0 + bias[j];
                    float gv = v1 + bias[j + ldc];
                    float act = av / (1.f + expf(-gv));
                    if (Res) act *= Res[(row / TT) * (long)ldc + j];
                    uint16_t h, l; split1(act, h, l);
                    // quad-pack: 4 consecutive j per quad -> one 8B store x3
                    uint hv = h, lv = l;
                    uint hn = __shfl_xor_sync(0xffffffffu, hv, 1);
                    uint lw = __shfl_xor_sync(0xffffffffu, lv, 1);
                    uint hpair = hv | (hn << 16);
                    uint lpair = lv | (lw << 16);
                    uint hp2 = __shfl_xor_sync(0xffffffffu, hpair, 2);
                    uint lp2 = __shfl_xor_sync(0xffffffffu, lpair, 2);
                    if ((lane & 3) == 0){
                        __half* o = Ch + row * (3L * ldc) + j;
                        uint2 hq; hq.x = hpair; hq.y = hp2;
                        uint2 lq; lq.x = lpair; lq.y = lp2;
                        *(uint2*)(o)           = hq;
                        *(uint2*)(o + ldc)     = hq;
                        *(uint2*)(o + 2 * ldc) = lq;
                    }
                } else {
                    // EPI 4/5: split-write pair (col,col+1); ldc = N
                    if (bias){ v0 += bias[col]; v1 += bias[col + 1]; }
                    if (EPI == 4){
                        float2 q = *(const float2*)&Res[row * (long)ldc + col];
                        v0 += q.x; v1 += q.y;
                    }
                    uint16_t h0, l0, h1, l1;
                    split1(v0, h0, l0); split1(v1, h1, l1);
                    __half* o = Ch + row * (3L * ldc) + col;
                    uint hp = (uint)h0 | ((uint)h1 << 16);
                    uint lp = (uint)l0 | ((uint)l1 << 16);
                    *(uint*)(o)           = hp;
                    *(uint*)(o + ldc)     = hp;
                    *(uint*)(o + 2 * ldc) = lp;
                }
            }
        }
    }
}

// ---------------- LayerNorm: f32 row -> optional f32 + fp16 split ----------
__global__ __launch_bounds__(256) void ln_kernel(
    const float* __restrict__ X, const float* __restrict__ g,
    const float* __restrict__ b, float* __restrict__ Y, __half* __restrict__ O)
{
    long row = blockIdx.x;
    const float* xr = X + row * CC;
    int t = threadIdx.x;
    float v0 = xr[t], v1 = xr[t + 256], v2 = xr[t + 512];
    float s  = v0 + v1 + v2;
    float s2 = v0*v0 + v1*v1 + v2*v2;
    __shared__ float sh[64];
    #pragma unroll
    for (int o = 16; o > 0; o >>= 1){
        s  += __shfl_down_sync(0xffffffffu, s,  o);
        s2 += __shfl_down_sync(0xffffffffu, s2, o);
    }
    int w = t >> 5, l = t & 31;
    if (l == 0){ sh[w] = s; sh[w + 32] = s2; }
    __syncthreads();
    if (w == 0){
        s  = (l < 8) ? sh[l]      : 0.f;
        s2 = (l < 8) ? sh[l + 32] : 0.f;
        #pragma unroll
        for (int o = 4; o > 0; o >>= 1){
            s  += __shfl_down_sync(0xffffffffu, s,  o);
            s2 += __shfl_down_sync(0xffffffffu, s2, o);
        }
        if (l == 0){ sh[0] = s; sh[1] = s2; }
    }
    __syncthreads();
    float mu  = sh[0] * (1.0f / CC);
    float var = sh[1] * (1.0f / CC) - mu * mu;
    float inv = rsqrtf(var + 1e-6f);
    __half* orow = O + row * 2304L;
    float* yr = Y ? (Y + row * CC) : nullptr;
    #pragma unroll
    for (int q = 0; q < 3; q++){
        int j = t + q * 256;
        float y = (q == 0 ? v0 : (q == 1 ? v1 : v2));
        y = (y - mu) * inv * g[j] + b[j];
        if (Y) yr[j] = y;
        uint16_t h, lo2; split1(y, h, lo2);
        orow[j]        = __ushort_as_half(h);
        orow[768 + j]  = __ushort_as_half(h);
        orow[1536 + j] = __ushort_as_half(lo2);
    }
}

// transpose+split: X[R,Cn] f32 (batched) -> O[Cn,3R] fp16
// AORDER: [hi|hi|lo], else B-order [hi|lo|hi].  block (32,8)
template<bool AORDER>
__global__ void splitT_kernel(const float* __restrict__ X, long sIn,
                              __half* __restrict__ O, long sOut, int R, int Cn)
{
    int bz = blockIdx.z;
    X += (long)bz * sIn;  O += (long)bz * sOut;
    __shared__ float tile[32][33];
    int r0 = blockIdx.y * 32, c0 = blockIdx.x * 32;
    int tx = threadIdx.x, ty = threadIdx.y;
    #pragma unroll
    for (int i = 0; i < 32; i += 8)
        tile[ty + i][tx] = X[(long)(r0 + ty + i) * Cn + c0 + tx];
    __syncthreads();
    #pragma unroll
    for (int i = 0; i < 32; i += 8){
        int c = c0 + ty + i, r = r0 + tx;
        float v = tile[tx][ty + i];
        uint16_t h, lo2; split1(v, h, lo2);
        long base = (long)c * (3L * R);
        O[base + r] = __ushort_as_half(h);
        if (AORDER){
            O[base + R + r]      = __ushort_as_half(h);
            O[base + 2L * R + r] = __ushort_as_half(lo2);
        } else {
            O[base + R + r]      = __ushort_as_half(lo2);
            O[base + 2L * R + r] = __ushort_as_half(h);
        }
    }
}

// transpose+split with gate-pairing: W[K, 2Kh] -> O[2Kh, 3K] B-order,
// output row for orig col c: c<Kh ? 2c : 2(c-Kh)+1
__global__ void splitT_pair_kernel(const float* __restrict__ X,
                                   __half* __restrict__ O, int R, int Cn, int Kh)
{
    __shared__ float tile[32][33];
    int r0 = blockIdx.y * 32, c0 = blockIdx.x * 32;
    int tx = threadIdx.x, ty = threadIdx.y;
    #pragma unroll
    for (int i = 0; i < 32; i += 8)
        tile[ty + i][tx] = X[(long)(r0 + ty + i) * Cn + c0 + tx];
    __syncthreads();
    #pragma unroll
    for (int i = 0; i < 32; i += 8){
        int c = c0 + ty + i, r = r0 + tx;
        int nn = (c < Kh) ? (2 * c) : (2 * (c - Kh) + 1);
        float v = tile[tx][ty + i];
        uint16_t h, lo2; split1(v, h, lo2);
        long base = (long)nn * (3L * R);
        O[base + r]          = __ushort_as_half(h);
        O[base + R + r]      = __ushort_as_half(lo2);
        O[base + 2L * R + r] = __ushort_as_half(h);
    }
}

// ---------------- style vector: S[b,n] = w_row[b] @ sW + sb ----------------
__global__ __launch_bounds__(256) void style_kernel(
    const float* __restrict__ w, int wOff,
    const float* __restrict__ sW, const float* __restrict__ sb,
    float* __restrict__ S, int N)
{
    int b = blockIdx.y;
    int nl = threadIdx.x & 63, kg = threadIdx.x >> 6;
    int n = blockIdx.x * 64 + nl;
    __shared__ float ws[WDD];
    __shared__ float red[256];
    const float* wr = w + (long)b * 2 * WDD + wOff;
    for (int i = threadIdx.x; i < WDD; i += 256) ws[i] = wr[i];
    __syncthreads();
    float acc = 0.f;
    #pragma unroll 4
    for (int k = kg * 128; k < kg * 128 + 128; k++)
        acc = fmaf(ws[k], sW[(long)k * N + n], acc);
    red[threadIdx.x] = acc;
    __syncthreads();
    if (kg == 0)
        S[(long)b * N + n] = red[nl] + red[64+nl] + red[128+nl] + red[192+nl] + sb[n];
}

// ---------------- host orchestration ----------------
extern "C" void kernel_launch(void* const* d_in, const int* in_sizes, int n_in,
                              void* d_out, int out_size)
{
    const float* x     = (const float*)d_in[0];
    const float* w     = (const float*)d_in[1];
    const float* ln1_g = (const float*)d_in[2];
    const float* ln1_b = (const float*)d_in[3];
    const float* ln2_g = (const float*)d_in[4];
    const float* ln2_b = (const float*)d_in[5];
    const float* g1_W  = (const float*)d_in[6];
    const float* g1_b  = (const float*)d_in[7];
    const float* s1_W  = (const float*)d_in[8];
    const float* s1_b  = (const float*)d_in[9];
    const float* m1_W  = (const float*)d_in[10];
    const float* m1_b  = (const float*)d_in[11];
    const float* g2_W  = (const float*)d_in[12];
    const float* g2_b  = (const float*)d_in[13];
    const float* s2_W  = (const float*)d_in[14];
    const float* s2_b  = (const float*)d_in[15];
    const float* m2_W  = (const float*)d_in[16];
    const float* m2_b  = (const float*)d_in[17];
    const float* gs_W  = (const float*)d_in[18];
    const float* gs_b  = (const float*)d_in[19];
    const float* ss_W  = (const float*)d_in[20];
    const float* ss_b  = (const float*)d_in[21];
    const float* ms_W  = (const float*)d_in[22];
    const float* ms_b  = (const float*)d_in[23];
    const float* r1_W  = (const float*)d_in[24];
    const float* r1_b  = (const float*)d_in[25];
    const float* r2_W  = (const float*)d_in[26];
    const float* r2_b  = (const float*)d_in[27];
    float* out = (float*)d_out;

    float *XLN,*H1,*MIX,*X1,*S1,*S2,*SS;
    __half *XLNh,*ACT,*H2h,*X2h,*H1T,*XLNT,*MIXT;
    __half *Wg1,*Wg2,*Wr1,*Wm1,*Wm2,*Wr2,*Wgs,*Wms;
    cudaGetSymbolAddress((void**)&XLN, g_XLN);
    cudaGetSymbolAddress((void**)&H1, g_H1);
    cudaGetSymbolAddress((void**)&MIX, g_MIX);   cudaGetSymbolAddress((void**)&X1, g_X1);
    cudaGetSymbolAddress((void**)&S1, g_S1);     cudaGetSymbolAddress((void**)&S2, g_S2);
    cudaGetSymbolAddress((void**)&SS, g_SS);
    cudaGetSymbolAddress((void**)&XLNh, h_XLN);  cudaGetSymbolAddress((void**)&ACT, h_ACT);
    cudaGetSymbolAddress((void**)&H2h, h_H2);    cudaGetSymbolAddress((void**)&X2h, h_X2);
    cudaGetSymbolAddress((void**)&H1T, h_H1T);   cudaGetSymbolAddress((void**)&XLNT, h_XLNT);
    cudaGetSymbolAddress((void**)&MIXT, h_MIXT);
    cudaGetSymbolAddress((void**)&Wg1, h_Wg1);   cudaGetSymbolAddress((void**)&Wg2, h_Wg2);
    cudaGetSymbolAddress((void**)&Wr1, h_Wr1);   cudaGetSymbolAddress((void**)&Wm1, h_Wm1);
    cudaGetSymbolAddress((void**)&Wm2, h_Wm2);   cudaGetSymbolAddress((void**)&Wr2, h_Wr2);
    cudaGetSymbolAddress((void**)&Wgs, h_Wgs);   cudaGetSymbolAddress((void**)&Wms, h_Wms);

    cudaFuncSetAttribute(hgemm<0>, cudaFuncAttributeMaxDynamicSharedMemorySize, HSMEMB);
    cudaFuncSetAttribute(hgemm<1>, cudaFuncAttributeMaxDynamicSharedMemorySize, HSMEMB);
    cudaFuncSetAttribute(hgemm<2>, cudaFuncAttributeMaxDynamicSharedMemorySize, HSMEMB);
    cudaFuncSetAttribute(hgemm<3>, cudaFuncAttributeMaxDynamicSharedMemorySize, HSMEMB);
    cudaFuncSetAttribute(hgemm<4>, cudaFuncAttributeMaxDynamicSharedMemorySize, HSMEMB);
    cudaFuncSetAttribute(hgemm<5>, cudaFuncAttributeMaxDynamicSharedMemorySize, HSMEMB);

    dim3 tb(32, 8);

    // gate weights -> paired [2Kh, 3K]; others -> plain B-order [N, 3K]
    splitT_pair_kernel<<<dim3(768/32, 768/32), tb>>>(g1_W, Wg1, 768, 768, 384);
    splitT_pair_kernel<<<dim3(768/32, 768/32), tb>>>(g2_W, Wg2, 768, 768, 384);
    splitT_pair_kernel<<<dim3(768/32, 768/32), tb>>>(r1_W, Wr1, 768, 768, 384);
    splitT_pair_kernel<<<dim3(3072/32, 768/32), tb>>>(gs_W, Wgs, 768, 3072, 1536);
    splitT_kernel<false><<<dim3(384/32, 384/32, 1), tb>>>(m1_W, 0, Wm1, 0, 384, 384);
    splitT_kernel<false><<<dim3(384/32, 384/32, 1), tb>>>(m2_W, 0, Wm2, 0, 384, 384);
    splitT_kernel<false><<<dim3(768/32, 384/32, 1), tb>>>(r2_W, 0, Wr2, 0, 384, 768);
    splitT_kernel<false><<<dim3(768/32, 1536/32, 1), tb>>>(ms_W, 0, Wms, 0, 1536, 768);

    // style vectors
    style_kernel<<<dim3(HH1/64, BB), 256>>>(w, 0,   s1_W, s1_b, S1, HH1);
    style_kernel<<<dim3(HH1/64, BB), 256>>>(w, 0,   s2_W, s2_b, S2, HH1);
    style_kernel<<<dim3(HHS/64, BB), 256>>>(w, WDD, ss_W, ss_b, SS, HHS);

    // LN1 -> XLN f32 + fp16 split
    ln_kernel<<<MTOT, 256>>>(x, ln1_g, ln1_b, XLN, XLNh);
    splitT_kernel<false><<<dim3(CC/32, TT/32, BB), tb>>>(
        XLN, (long)TT*CC, XLNT, (long)CC*6144, TT, CC);

    // GLU #1: fused gate -> ACT ; H1 = ACT@m1_W + b (f32; needed for transpose)
    hgemm<3><<<dim3(CC/128, MTOT/128, 1), 256, HSMEMB>>>(
        XLNh, 0, 2304, Wg1, 0, 2304, ACT, 0, HH1, g1_b, S1, 0, 2304);
    hgemm<0><<<dim3(TDD/128, MTOT/128, 1), 256, HSMEMB>>>(
        ACT, 0, 1152, Wm1, 0, 1152, H1, 0, TDD, m1_b, nullptr, 0, 1152);

    // GLU #2: fused gate -> ACT ; H2h = split(ACT@m2_W + b) directly
    hgemm<3><<<dim3(CC/128, MTOT/128, 1), 256, HSMEMB>>>(
        XLNh, 0, 2304, Wg2, 0, 2304, ACT, 0, HH1, g2_b, S2, 0, 2304);
    hgemm<5><<<dim3(TDD/128, MTOT/128, 1), 256, HSMEMB>>>(
        ACT, 0, 1152, Wm2, 0, 1152, H2h, 0, TDD, m2_b, nullptr, 0, 1152);

    // transpose-split H1 for mix
    splitT_kernel<true ><<<dim3(TDD/32, TT/32, BB), tb>>>(
        H1, (long)TT*TDD, H1T, (long)TDD*6144, TT, TDD);

    // MIX[b] = gelu(H1[b]^T @ XLN[b])  M=384, N=768, K'=6144
    hgemm<1><<<dim3(CC/128, TDD/128, BB), 256, HSMEMB>>>(
        H1T, (long)TDD*6144, 6144, XLNT, (long)CC*6144, 6144,
        MIX, (long)TDD*CC, CC, nullptr, nullptr, 0, 6144);
    splitT_kernel<false><<<dim3(CC/32, TDD/32, BB), tb>>>(
        MIX, (long)TDD*CC, MIXT, (long)CC*1152, TDD, CC);

    // X1[b] = XLN[b] + H2[b] @ MIX[b]  (f32; feeds LN2 + ms residual)
    hgemm<2><<<dim3(CC/128, TT/128, BB), 256, HSMEMB>>>(
        H2h, (long)TT*1152, 1152, MIXT, (long)CC*1152, 1152,
        X1, (long)TT*CC, CC, nullptr, XLN, (long)TT*CC, 1152);

    // LN2 -> fp16 split only
    ln_kernel<<<MTOT, 256>>>(X1, ln2_g, ln2_b, nullptr, XLNh);

    // big GLU: fused gate (N=3072) -> ACT ; X2h = split(X1 + ACT@ms_W + b)
    hgemm<3><<<dim3(CDD/128, MTOT/128, 1), 256, HSMEMB>>>(
        XLNh, 0, 2304, Wgs, 0, 2304, ACT, 0, HHS, gs_b, SS, 0, 2304);
    hgemm<4><<<dim3(CC/128, MTOT/128, 1), 256, HSMEMB>>>(
        ACT, 0, 4608, Wms, 0, 4608, X2h, 0, CC, ms_b, X1, 0, 4608);

    // final GLU: fused gate (no style) -> ACT ; out = ACT@r2_W + b
    hgemm<3><<<dim3(CC/128, MTOT/128, 1), 256, HSMEMB>>>(
        X2h, 0, 2304, Wr1, 0, 2304, ACT, 0, HH1, r1_b, nullptr, 0, 2304);
    hgemm<0><<<dim3(CC/128, MTOT/128, 1), 256, HSMEMB>>>(
        ACT, 0, 1152, Wr2, 0, 1152, out, 0, CC, r2_b, nullptr, 0, 1152);
}